// round 1
// baseline (speedup 1.0000x reference)
#include <cuda_runtime.h>
#include <cuda_bf16.h>
#include <math.h>

// Problem constants
#define BB      2
#define TT      2048
#define NH      12
#define DH      64
#define CC      768      // d_model
#define C3      2304     // 3*d_model
#define MM      (BB*TT)  // 4096 rows

// Scratch (device globals — no runtime allocation allowed)
__device__ float g_qkv[(size_t)MM * C3];     // [4096, 2304]
__device__ float g_att[(size_t)MM * CC];     // [4096, 768]

// ---------------------------------------------------------------------------
// Tiled FP32 GEMM with bias: C[M,N] = A[M,K] @ B[K,N] + bias[N]
// BM=128, BN=64, BK=16, 256 threads, 8x4 per-thread microtile.
// Requires M%128==0, N%64==0, K%16==0 (true for all shapes here).
// ---------------------------------------------------------------------------
__global__ __launch_bounds__(256)
void gemm_bias_kernel(const float* __restrict__ A, const float* __restrict__ B,
                      const float* __restrict__ bias, float* __restrict__ C,
                      int M, int N, int K)
{
    const int BM = 128, BN = 64, BK = 16, TM = 8, TN = 4;
    __shared__ float As[BK][BM];   // transposed A tile
    __shared__ float Bs[BK][BN];

    const int tid = threadIdx.x;
    const int tx  = tid & 15;      // 0..15 (N direction)
    const int ty  = tid >> 4;      // 0..15 (M direction)
    const int rowBase = blockIdx.y * BM;
    const int colBase = blockIdx.x * BN;

    float acc[TM][TN];
#pragma unroll
    for (int i = 0; i < TM; i++)
#pragma unroll
        for (int j = 0; j < TN; j++) acc[i][j] = 0.f;

    for (int k0 = 0; k0 < K; k0 += BK) {
        // Load A tile: 128x16 = 512 float4, 2 per thread, store transposed
#pragma unroll
        for (int it = 0; it < 2; ++it) {
            int idx = it * 256 + tid;          // 0..511
            int r   = idx >> 2;                // row within tile
            int c4  = idx & 3;                 // float4 index in k
            float4 v = *(const float4*)(A + (size_t)(rowBase + r) * K + k0 + c4 * 4);
            As[c4 * 4 + 0][r] = v.x;
            As[c4 * 4 + 1][r] = v.y;
            As[c4 * 4 + 2][r] = v.z;
            As[c4 * 4 + 3][r] = v.w;
        }
        // Load B tile: 16x64 = 256 float4, 1 per thread
        {
            int kk = tid >> 4;                 // 0..15
            int c4 = tid & 15;                 // 0..15
            float4 v = *(const float4*)(B + (size_t)(k0 + kk) * N + colBase + c4 * 4);
            *(float4*)&Bs[kk][c4 * 4] = v;
        }
        __syncthreads();

#pragma unroll
        for (int kk = 0; kk < BK; ++kk) {
            float a[TM], b[TN];
#pragma unroll
            for (int i = 0; i < TM; i++) a[i] = As[kk][ty * TM + i];
#pragma unroll
            for (int j = 0; j < TN; j++) b[j] = Bs[kk][tx * TN + j];
#pragma unroll
            for (int i = 0; i < TM; i++)
#pragma unroll
                for (int j = 0; j < TN; j++)
                    acc[i][j] = fmaf(a[i], b[j], acc[i][j]);
        }
        __syncthreads();
    }

    // Epilogue with bias, float4 stores (TN==4)
    float4 bv = *(const float4*)(bias + colBase + tx * 4);
#pragma unroll
    for (int i = 0; i < TM; i++) {
        int r = rowBase + ty * TM + i;
        float4 o;
        o.x = acc[i][0] + bv.x;
        o.y = acc[i][1] + bv.y;
        o.z = acc[i][2] + bv.z;
        o.w = acc[i][3] + bv.w;
        *(float4*)(C + (size_t)r * N + colBase + tx * 4) = o;
    }
}

// ---------------------------------------------------------------------------
// Causal flash attention, fp32. One query row per thread, 128 rows per block.
// K/V tiles of 64 keys in shared memory (float4). Online softmax in chunks of
// 8 keys. qkv layout: [4096, 2304] where q|k|v occupy cols [0,768)|[768,1536)|
// [1536,2304); head h uses cols h*64..h*64+63 of each.
// ---------------------------------------------------------------------------
__global__ __launch_bounds__(128)
void flash_attn_kernel(const float* __restrict__ qkv, float* __restrict__ out)
{
    const int b   = blockIdx.z;
    const int h   = blockIdx.y;
    const int q0  = blockIdx.x * 128;
    const int tid = threadIdx.x;
    const int qrow = q0 + tid;

    __shared__ float4 Ks[64][16];
    __shared__ float4 Vs[64][16];

    const float scale = 0.125f;   // 1/sqrt(64)
    const float NEG   = -1e38f;

    // Load this thread's query row (64 floats)
    float4 q[16];
    {
        const float* qp = qkv + (size_t)(b * TT + qrow) * C3 + h * DH;
#pragma unroll
        for (int i = 0; i < 16; i++) q[i] = *(const float4*)(qp + i * 4);
    }

    float4 o[16];
#pragma unroll
    for (int i = 0; i < 16; i++) o[i] = make_float4(0.f, 0.f, 0.f, 0.f);
    float m = NEG, l = 0.f;

    const int kend = q0 + 128;   // exclusive bound on keys for this block

    for (int k0 = 0; k0 < kend; k0 += 64) {
        __syncthreads();
        // Load K and V tiles: 64 keys x 16 float4 each; 8 float4-pairs/thread
#pragma unroll
        for (int it = 0; it < 8; ++it) {
            int idx = it * 128 + tid;
            int j   = idx >> 4;
            int c4  = idx & 15;
            const float* kp = qkv + (size_t)(b * TT + k0 + j) * C3 + CC + h * DH;
            Ks[j][c4] = *(const float4*)(kp + c4 * 4);
            Vs[j][c4] = *(const float4*)(kp + CC + c4 * 4);
        }
        __syncthreads();

#pragma unroll 1
        for (int jc = 0; jc < 64; jc += 8) {
            if (k0 + jc > qrow) break;   // this chunk (and all later) fully masked

            float s[8];
#pragma unroll
            for (int jj = 0; jj < 8; jj++) {
                float acc = 0.f;
#pragma unroll
                for (int d = 0; d < 16; ++d) {
                    float4 kk = Ks[jc + jj][d];
                    acc = fmaf(q[d].x, kk.x, acc);
                    acc = fmaf(q[d].y, kk.y, acc);
                    acc = fmaf(q[d].z, kk.z, acc);
                    acc = fmaf(q[d].w, kk.w, acc);
                }
                acc *= scale;
                s[jj] = (k0 + jc + jj > qrow) ? NEG : acc;
            }

            float mc = s[0];
#pragma unroll
            for (int jj = 1; jj < 8; jj++) mc = fmaxf(mc, s[jj]);
            float mnew = fmaxf(m, mc);

            float corr = __expf(m - mnew);
            l *= corr;
#pragma unroll
            for (int d = 0; d < 16; d++) {
                o[d].x *= corr; o[d].y *= corr; o[d].z *= corr; o[d].w *= corr;
            }

            float p[8];
#pragma unroll
            for (int jj = 0; jj < 8; jj++) {
                p[jj] = __expf(s[jj] - mnew);
                l += p[jj];
            }
#pragma unroll
            for (int jj = 0; jj < 8; jj++) {
                float pj = p[jj];
#pragma unroll
                for (int d = 0; d < 16; d++) {
                    float4 vv = Vs[jc + jj][d];
                    o[d].x = fmaf(pj, vv.x, o[d].x);
                    o[d].y = fmaf(pj, vv.y, o[d].y);
                    o[d].z = fmaf(pj, vv.z, o[d].z);
                    o[d].w = fmaf(pj, vv.w, o[d].w);
                }
            }
            m = mnew;
        }
    }

    const float inv = 1.f / l;
    float* op = out + (size_t)(b * TT + qrow) * CC + h * DH;
#pragma unroll
    for (int d = 0; d < 16; d++) {
        float4 r;
        r.x = o[d].x * inv; r.y = o[d].y * inv;
        r.z = o[d].z * inv; r.w = o[d].w * inv;
        *(float4*)(op + d * 4) = r;
    }
}

// ---------------------------------------------------------------------------
// kernel_launch: x, mask, Wqkv, bqkv, Wout, bout -> out [2,2048,768] fp32
// ---------------------------------------------------------------------------
extern "C" void kernel_launch(void* const* d_in, const int* in_sizes, int n_in,
                              void* d_out, int out_size)
{
    const float* x    = (const float*)d_in[0];
    // d_in[1] = mask (causal, known statically; unused)
    const float* Wqkv = (const float*)d_in[2];
    const float* bqkv = (const float*)d_in[3];
    const float* Wout = (const float*)d_in[4];
    const float* bout = (const float*)d_in[5];
    float* out = (float*)d_out;

    float* qkv; cudaGetSymbolAddress((void**)&qkv, g_qkv);
    float* att; cudaGetSymbolAddress((void**)&att, g_att);

    // 1) QKV projection: [4096,768] @ [768,2304] + bias
    {
        dim3 grid(C3 / 64, MM / 128);
        gemm_bias_kernel<<<grid, 256>>>(x, Wqkv, bqkv, qkv, MM, C3, CC);
    }
    // 2) Causal multi-head attention
    {
        dim3 grid(TT / 128, NH, BB);
        flash_attn_kernel<<<grid, 128>>>(qkv, att);
    }
    // 3) Output projection: [4096,768] @ [768,768] + bias
    {
        dim3 grid(CC / 64, MM / 128);
        gemm_bias_kernel<<<grid, 256>>>(att, Wout, bout, out, MM, CC, CC);
    }
}

// round 2
// speedup vs baseline: 5.0158x; 5.0158x over previous
#include <cuda_runtime.h>

// Problem constants
#define BB      2
#define TT      2048
#define NH      12
#define DH      64
#define CC      768      // d_model
#define C3      2304     // 3*d_model
#define MM      (BB*TT)  // 4096 rows

// Scratch (device globals — no runtime allocation allowed)
__device__ float g_qkv[(size_t)MM * C3];     // [4096, 2304]
__device__ float g_att[(size_t)MM * CC];     // [4096, 768]

// ---------------------------------------------------------------------------
// helpers
// ---------------------------------------------------------------------------
__device__ __forceinline__ unsigned f2tf(float f) {
    unsigned u; asm("cvt.rna.tf32.f32 %0, %1;" : "=r"(u) : "f"(f)); return u;
}
__device__ __forceinline__ float ex2f(float x) {
    float r; asm("ex2.approx.f32 %0, %1;" : "=f"(r) : "f"(x)); return r;
}
__device__ __forceinline__ void mma_tf32(float c[4], const unsigned a[4], const unsigned b[2]) {
    asm volatile(
        "mma.sync.aligned.m16n8k8.row.col.f32.tf32.tf32.f32 "
        "{%0,%1,%2,%3},{%4,%5,%6,%7},{%8,%9},{%0,%1,%2,%3};"
        : "+f"(c[0]), "+f"(c[1]), "+f"(c[2]), "+f"(c[3])
        : "r"(a[0]), "r"(a[1]), "r"(a[2]), "r"(a[3]), "r"(b[0]), "r"(b[1]));
}

// ---------------------------------------------------------------------------
// TF32 tensor-core GEMM with bias: C[M,N] = A[M,K] @ B[K,N] + bias[N]
// 128x128 block tile, BK=32, 256 threads (8 warps, 2x4), warp tile 64x32.
// Requires M%128==0, N%128==0, K%32==0.
// ---------------------------------------------------------------------------
__global__ __launch_bounds__(256)
void gemm_tf32(const float* __restrict__ A, const float* __restrict__ B,
               const float* __restrict__ bias, float* __restrict__ C,
               int M, int N, int K)
{
    __shared__ __align__(16) unsigned As[128][36];   // [m][k], pad 4 -> bank 4m+k
    __shared__ __align__(16) unsigned Bs[32][136];   // [k][n], pad 8 -> bank 8k+n

    const int tid  = threadIdx.x;
    const int lane = tid & 31;
    const int w    = tid >> 5;
    const int wm   = (w >> 2) * 64;    // warp M offset (0 or 64)
    const int wn   = (w & 3) * 32;     // warp N offset
    const int g    = lane >> 2;        // group id 0..7
    const int tig  = lane & 3;         // thread-in-group 0..3
    const int rowBase = blockIdx.y * 128;
    const int colBase = blockIdx.x * 128;

    float acc[4][4][4];
#pragma unroll
    for (int mt = 0; mt < 4; mt++)
#pragma unroll
        for (int nt = 0; nt < 4; nt++)
#pragma unroll
            for (int j = 0; j < 4; j++) acc[mt][nt][j] = 0.f;

    const int ar  = tid >> 3;          // A row 0..31 (x4 iters)
    const int ac4 = tid & 7;           // A float4 col
    const int br  = tid >> 5;          // B row 0..7  (x4 iters)
    const int bc4 = tid & 31;          // B float4 col

    for (int k0 = 0; k0 < K; k0 += 32) {
#pragma unroll
        for (int i = 0; i < 4; i++) {
            float4 v = *(const float4*)(A + (size_t)(rowBase + ar + i * 32) * K + k0 + ac4 * 4);
            *(uint4*)&As[ar + i * 32][ac4 * 4] =
                make_uint4(f2tf(v.x), f2tf(v.y), f2tf(v.z), f2tf(v.w));
        }
#pragma unroll
        for (int i = 0; i < 4; i++) {
            float4 v = *(const float4*)(B + (size_t)(k0 + br + i * 8) * N + colBase + bc4 * 4);
            *(uint4*)&Bs[br + i * 8][bc4 * 4] =
                make_uint4(f2tf(v.x), f2tf(v.y), f2tf(v.z), f2tf(v.w));
        }
        __syncthreads();

#pragma unroll
        for (int ks = 0; ks < 4; ks++) {
            unsigned af[4][4], bf[4][2];
#pragma unroll
            for (int mt = 0; mt < 4; mt++) {
                int m = wm + mt * 16 + g;
                af[mt][0] = As[m][ks * 8 + tig];
                af[mt][1] = As[m + 8][ks * 8 + tig];
                af[mt][2] = As[m][ks * 8 + tig + 4];
                af[mt][3] = As[m + 8][ks * 8 + tig + 4];
            }
#pragma unroll
            for (int nt = 0; nt < 4; nt++) {
                int n = wn + nt * 8 + g;
                bf[nt][0] = Bs[ks * 8 + tig][n];
                bf[nt][1] = Bs[ks * 8 + tig + 4][n];
            }
#pragma unroll
            for (int mt = 0; mt < 4; mt++)
#pragma unroll
                for (int nt = 0; nt < 4; nt++)
                    mma_tf32(acc[mt][nt], af[mt], bf[nt]);
        }
        __syncthreads();
    }

#pragma unroll
    for (int mt = 0; mt < 4; mt++) {
        int r0 = rowBase + wm + mt * 16 + g;
#pragma unroll
        for (int nt = 0; nt < 4; nt++) {
            int c = colBase + wn + nt * 8 + 2 * tig;
            float2 b2 = *(const float2*)(bias + c);
            float2 o0, o1;
            o0.x = acc[mt][nt][0] + b2.x;  o0.y = acc[mt][nt][1] + b2.y;
            o1.x = acc[mt][nt][2] + b2.x;  o1.y = acc[mt][nt][3] + b2.y;
            *(float2*)(C + (size_t)r0 * N + c)       = o0;
            *(float2*)(C + (size_t)(r0 + 8) * N + c) = o1;
        }
    }
}

// ---------------------------------------------------------------------------
// Causal flash attention, TF32 tensor cores.
// Block: 64 queries (one (b,h)), 4 warps x 16 queries. Key tiles of 64.
// Dynamic smem: QP[64][68] (Q tf32, reused as P staging) | Ks[64][68] | Vs[64][72]
// ---------------------------------------------------------------------------
__global__ __launch_bounds__(128)
void flash_tf32(const float* __restrict__ qkv, float* __restrict__ out)
{
    extern __shared__ unsigned sm[];
    unsigned (*QP)[68] = (unsigned(*)[68])sm;                  // bank: 4m+k
    unsigned (*Ks)[68] = (unsigned(*)[68])(sm + 64 * 68);      // bank: 4n+k
    unsigned (*Vs)[72] = (unsigned(*)[72])(sm + 2 * 64 * 68);  // bank: 8k+n

    const int b   = blockIdx.z;
    const int h   = blockIdx.y;
    const int qb  = blockIdx.x;
    const int tid = threadIdx.x;
    const int lane = tid & 31;
    const int w    = tid >> 5;
    const int g    = lane >> 2;
    const int tig  = lane & 3;
    const int m0   = w * 16;

    // fold softmax scale and log2(e) into Q
    const float qscale = 0.125f * 1.44269504088896341f;

    // ---- load Q tile (scaled, tf32) ----
    {
        const float* qp = qkv + (size_t)(b * TT + qb * 64) * C3 + h * DH;
#pragma unroll
        for (int i = 0; i < 8; i++) {
            int idx = tid + i * 128;
            int r = idx >> 4, c4 = idx & 15;
            float4 v = *(const float4*)(qp + (size_t)r * C3 + c4 * 4);
            *(uint4*)&QP[r][c4 * 4] = make_uint4(
                f2tf(v.x * qscale), f2tf(v.y * qscale),
                f2tf(v.z * qscale), f2tf(v.w * qscale));
        }
    }
    __syncthreads();

    // ---- extract persistent Q fragments ----
    unsigned qf[8][4];
#pragma unroll
    for (int kt = 0; kt < 8; kt++) {
        qf[kt][0] = QP[m0 + g][kt * 8 + tig];
        qf[kt][1] = QP[m0 + 8 + g][kt * 8 + tig];
        qf[kt][2] = QP[m0 + g][kt * 8 + tig + 4];
        qf[kt][3] = QP[m0 + 8 + g][kt * 8 + tig + 4];
    }
    __syncthreads();   // QP now reusable as P staging

    float o[8][4];
#pragma unroll
    for (int nt = 0; nt < 8; nt++)
#pragma unroll
        for (int j = 0; j < 4; j++) o[nt][j] = 0.f;

    float mr0 = -1e30f, mr1 = -1e30f, l0 = 0.f, l1 = 0.f;
    const int qg0 = qb * 64 + m0 + g;      // global row of c0/c1
    const int qg1 = qg0 + 8;               // global row of c2/c3

    for (int kb = 0; kb <= qb; kb++) {
        __syncthreads();
        // ---- load K, V tiles ----
        {
            const float* kp = qkv + (size_t)(b * TT + kb * 64) * C3 + CC + h * DH;
#pragma unroll
            for (int i = 0; i < 8; i++) {
                int idx = tid + i * 128;
                int r = idx >> 4, c4 = idx & 15;
                const float* rp = kp + (size_t)r * C3 + c4 * 4;
                float4 kv = *(const float4*)rp;
                *(uint4*)&Ks[r][c4 * 4] =
                    make_uint4(f2tf(kv.x), f2tf(kv.y), f2tf(kv.z), f2tf(kv.w));
                float4 vv = *(const float4*)(rp + CC);
                *(uint4*)&Vs[r][c4 * 4] =
                    make_uint4(f2tf(vv.x), f2tf(vv.y), f2tf(vv.z), f2tf(vv.w));
            }
        }
        __syncthreads();

        // ---- S = Q K^T ----
        float s[8][4];
#pragma unroll
        for (int nt = 0; nt < 8; nt++) {
            s[nt][0] = s[nt][1] = s[nt][2] = s[nt][3] = 0.f;
#pragma unroll
            for (int kt = 0; kt < 8; kt++) {
                unsigned bb[2];
                bb[0] = Ks[nt * 8 + g][kt * 8 + tig];
                bb[1] = Ks[nt * 8 + g][kt * 8 + tig + 4];
                mma_tf32(s[nt], qf[kt], bb);
            }
        }

        // ---- causal mask (diagonal block only) ----
        if (kb == qb) {
#pragma unroll
            for (int nt = 0; nt < 8; nt++) {
                int kg = kb * 64 + nt * 8 + 2 * tig;
                if (kg > qg0)     s[nt][0] = -1e30f;
                if (kg + 1 > qg0) s[nt][1] = -1e30f;
                if (kg > qg1)     s[nt][2] = -1e30f;
                if (kg + 1 > qg1) s[nt][3] = -1e30f;
            }
        }

        // ---- online softmax ----
        float vm0 = -1e30f, vm1 = -1e30f;
#pragma unroll
        for (int nt = 0; nt < 8; nt++) {
            vm0 = fmaxf(vm0, fmaxf(s[nt][0], s[nt][1]));
            vm1 = fmaxf(vm1, fmaxf(s[nt][2], s[nt][3]));
        }
        vm0 = fmaxf(vm0, __shfl_xor_sync(0xffffffffu, vm0, 1));
        vm0 = fmaxf(vm0, __shfl_xor_sync(0xffffffffu, vm0, 2));
        vm1 = fmaxf(vm1, __shfl_xor_sync(0xffffffffu, vm1, 1));
        vm1 = fmaxf(vm1, __shfl_xor_sync(0xffffffffu, vm1, 2));

        float mn0 = fmaxf(mr0, vm0), mn1 = fmaxf(mr1, vm1);
        float corr0 = ex2f(mr0 - mn0), corr1 = ex2f(mr1 - mn1);
        mr0 = mn0; mr1 = mn1;

        float sum0 = 0.f, sum1 = 0.f;
#pragma unroll
        for (int nt = 0; nt < 8; nt++) {
            s[nt][0] = ex2f(s[nt][0] - mn0);
            s[nt][1] = ex2f(s[nt][1] - mn0);
            s[nt][2] = ex2f(s[nt][2] - mn1);
            s[nt][3] = ex2f(s[nt][3] - mn1);
            sum0 += s[nt][0] + s[nt][1];
            sum1 += s[nt][2] + s[nt][3];
        }
        sum0 += __shfl_xor_sync(0xffffffffu, sum0, 1);
        sum0 += __shfl_xor_sync(0xffffffffu, sum0, 2);
        sum1 += __shfl_xor_sync(0xffffffffu, sum1, 1);
        sum1 += __shfl_xor_sync(0xffffffffu, sum1, 2);
        l0 = l0 * corr0 + sum0;
        l1 = l1 * corr1 + sum1;

#pragma unroll
        for (int nt = 0; nt < 8; nt++) {
            o[nt][0] *= corr0; o[nt][1] *= corr0;
            o[nt][2] *= corr1; o[nt][3] *= corr1;
        }

        // ---- stage P into QP (per-warp rows; warp-local sync suffices) ----
        __syncwarp();
#pragma unroll
        for (int nt = 0; nt < 8; nt++) {
            uint2 u0 = make_uint2(f2tf(s[nt][0]), f2tf(s[nt][1]));
            uint2 u1 = make_uint2(f2tf(s[nt][2]), f2tf(s[nt][3]));
            *(uint2*)&QP[m0 + g][nt * 8 + 2 * tig]     = u0;
            *(uint2*)&QP[m0 + 8 + g][nt * 8 + 2 * tig] = u1;
        }
        __syncwarp();

        // ---- O += P V ----
#pragma unroll
        for (int kt = 0; kt < 8; kt++) {
            unsigned pa[4];
            pa[0] = QP[m0 + g][kt * 8 + tig];
            pa[1] = QP[m0 + 8 + g][kt * 8 + tig];
            pa[2] = QP[m0 + g][kt * 8 + tig + 4];
            pa[3] = QP[m0 + 8 + g][kt * 8 + tig + 4];
#pragma unroll
            for (int nt = 0; nt < 8; nt++) {
                unsigned bb[2];
                bb[0] = Vs[kt * 8 + tig][nt * 8 + g];
                bb[1] = Vs[kt * 8 + tig + 4][nt * 8 + g];
                mma_tf32(o[nt], pa, bb);
            }
        }
    }

    // ---- normalize and write out ----
    const float inv0 = 1.f / l0, inv1 = 1.f / l1;
    float* op0 = out + (size_t)(b * TT + qb * 64 + m0 + g) * CC + h * DH;
    float* op1 = op0 + (size_t)8 * CC;
#pragma unroll
    for (int nt = 0; nt < 8; nt++) {
        float2 r0, r1;
        r0.x = o[nt][0] * inv0; r0.y = o[nt][1] * inv0;
        r1.x = o[nt][2] * inv1; r1.y = o[nt][3] * inv1;
        *(float2*)(op0 + nt * 8 + 2 * tig) = r0;
        *(float2*)(op1 + nt * 8 + 2 * tig) = r1;
    }
}

// ---------------------------------------------------------------------------
// kernel_launch
// ---------------------------------------------------------------------------
extern "C" void kernel_launch(void* const* d_in, const int* in_sizes, int n_in,
                              void* d_out, int out_size)
{
    const float* x    = (const float*)d_in[0];
    // d_in[1] = mask (static causal; unused)
    const float* Wqkv = (const float*)d_in[2];
    const float* bqkv = (const float*)d_in[3];
    const float* Wout = (const float*)d_in[4];
    const float* bout = (const float*)d_in[5];
    float* out = (float*)d_out;

    float* qkv; cudaGetSymbolAddress((void**)&qkv, g_qkv);
    float* att; cudaGetSymbolAddress((void**)&att, g_att);

    static bool configured = false;
    const int FLASH_SMEM = (2 * 64 * 68 + 64 * 72) * 4;   // 53248 bytes
    if (!configured) {
        cudaFuncSetAttribute(flash_tf32,
                             cudaFuncAttributeMaxDynamicSharedMemorySize, FLASH_SMEM);
        configured = true;
    }

    // 1) QKV projection: [4096,768] @ [768,2304] + bias
    {
        dim3 grid(C3 / 128, MM / 128);
        gemm_tf32<<<grid, 256>>>(x, Wqkv, bqkv, qkv, MM, C3, CC);
    }
    // 2) Causal multi-head attention
    {
        dim3 grid(TT / 64, NH, BB);
        flash_tf32<<<grid, 128, FLASH_SMEM>>>(qkv, att);
    }
    // 3) Output projection: [4096,768] @ [768,768] + bias
    {
        dim3 grid(CC / 128, MM / 128);
        gemm_tf32<<<grid, 256>>>(att, Wout, bout, out, MM, CC, CC);
    }
}

// round 3
// speedup vs baseline: 5.7029x; 1.1370x over previous
#include <cuda_runtime.h>

// Problem constants
#define BB      2
#define TT      2048
#define NH      12
#define DH      64
#define CC      768      // d_model
#define C3      2304     // 3*d_model
#define MM      (BB*TT)  // 4096 rows

// Scratch (device globals — no runtime allocation allowed)
__device__ float g_qkv[(size_t)MM * C3];     // [4096, 2304]  (tf32-rounded values)
__device__ float g_att[(size_t)MM * CC];     // [4096, 768]   (tf32-rounded values)
__device__ float g_xr[(size_t)MM * CC];      // x rounded
__device__ float g_wqkvr[(size_t)CC * C3];   // Wqkv rounded
__device__ float g_woutr[(size_t)CC * CC];   // Wout rounded

// ---------------------------------------------------------------------------
// helpers
// ---------------------------------------------------------------------------
__device__ __forceinline__ unsigned f2tf(float f) {
    unsigned u; asm("cvt.rna.tf32.f32 %0, %1;" : "=r"(u) : "f"(f)); return u;
}
__device__ __forceinline__ float ex2f(float x) {
    float r; asm("ex2.approx.f32 %0, %1;" : "=f"(r) : "f"(x)); return r;
}
__device__ __forceinline__ void mma_tf32(float c[4], const unsigned a[4], const unsigned b[2]) {
    asm volatile(
        "mma.sync.aligned.m16n8k8.row.col.f32.tf32.tf32.f32 "
        "{%0,%1,%2,%3},{%4,%5,%6,%7},{%8,%9},{%0,%1,%2,%3};"
        : "+f"(c[0]), "+f"(c[1]), "+f"(c[2]), "+f"(c[3])
        : "r"(a[0]), "r"(a[1]), "r"(a[2]), "r"(a[3]), "r"(b[0]), "r"(b[1]));
}
__device__ __forceinline__ void cp16(void* dst_smem, const void* src) {
    unsigned d = (unsigned)__cvta_generic_to_shared(dst_smem);
    asm volatile("cp.async.cg.shared.global [%0], [%1], 16;" :: "r"(d), "l"(src));
}
__device__ __forceinline__ void cp_commit() {
    asm volatile("cp.async.commit_group;");
}
template<int N> __device__ __forceinline__ void cp_wait() {
    asm volatile("cp.async.wait_group %0;" :: "n"(N));
}

// ---------------------------------------------------------------------------
// Pre-pass: round fp32 array to tf32 (rna) in one shot.
// ---------------------------------------------------------------------------
__global__ void round_tf32_kernel(const float* __restrict__ in, float* __restrict__ out, int n4)
{
    int i = blockIdx.x * blockDim.x + threadIdx.x;
    if (i < n4) {
        float4 v = ((const float4*)in)[i];
        uint4 u = make_uint4(f2tf(v.x), f2tf(v.y), f2tf(v.z), f2tf(v.w));
        ((float4*)out)[i] = *(float4*)&u;
    }
}

// ---------------------------------------------------------------------------
// TF32 tensor-core GEMM with bias, cp.async 2-stage pipeline.
// C[M,N] = A[M,K] @ B[K,N] + bias[N]. Inputs pre-rounded to tf32.
// 128x128 block tile, BK=32, 256 threads (8 warps), warp tile 64x32.
// Dynamic smem: 2 stages x (A[128][36] + B[32][136]) = 71680 B.
// If ROUND_OUT, output values are tf32-rounded (for tf32 consumers).
// ---------------------------------------------------------------------------
#define GA_W   (128*36)      // A stage words
#define GB_W   (32*136)      // B stage words
#define GSTAGE (GA_W + GB_W) // 8960 words
#define GEMM_SMEM (2 * GSTAGE * 4)

template<bool ROUND_OUT>
__global__ __launch_bounds__(256, 2)
void gemm_tf32_ca(const float* __restrict__ A, const float* __restrict__ B,
                  const float* __restrict__ bias, float* __restrict__ C,
                  int M, int N, int K)
{
    extern __shared__ unsigned smg[];

    const int tid  = threadIdx.x;
    const int lane = tid & 31;
    const int w    = tid >> 5;
    const int wm   = (w >> 2) * 64;
    const int wn   = (w & 3) * 32;
    const int g    = lane >> 2;
    const int tig  = lane & 3;
    const int rowBase = blockIdx.y * 128;
    const int colBase = blockIdx.x * 128;

    float acc[4][4][4];
#pragma unroll
    for (int mt = 0; mt < 4; mt++)
#pragma unroll
        for (int nt = 0; nt < 4; nt++)
#pragma unroll
            for (int j = 0; j < 4; j++) acc[mt][nt][j] = 0.f;

    auto loadTile = [&](int k0, int s) {
        unsigned* As = smg + s * GSTAGE;
        unsigned* Bs = smg + s * GSTAGE + GA_W;
        // A tile 128x32 floats = 1024 16B chunks (8/row)
#pragma unroll
        for (int i = 0; i < 4; i++) {
            int c = tid + i * 256;
            int r = c >> 3, c4 = c & 7;
            cp16(&As[r * 36 + c4 * 4], A + (size_t)(rowBase + r) * K + k0 + c4 * 4);
        }
        // B tile 32x128 floats = 1024 16B chunks (32/row)
#pragma unroll
        for (int i = 0; i < 4; i++) {
            int c = tid + i * 256;
            int r = c >> 5, c4 = c & 31;
            cp16(&Bs[r * 136 + c4 * 4], B + (size_t)(k0 + r) * N + colBase + c4 * 4);
        }
    };

    loadTile(0, 0);
    cp_commit();

    int buf = 0;
    for (int k0 = 0; k0 < K; k0 += 32) {
        if (k0 + 32 < K) { loadTile(k0 + 32, buf ^ 1); cp_commit(); cp_wait<1>(); }
        else             { cp_wait<0>(); }
        __syncthreads();

        unsigned (*As)[36]  = (unsigned(*)[36])(smg + buf * GSTAGE);
        unsigned (*Bs)[136] = (unsigned(*)[136])(smg + buf * GSTAGE + GA_W);

#pragma unroll
        for (int ks = 0; ks < 4; ks++) {
            unsigned af[4][4], bf[4][2];
#pragma unroll
            for (int mt = 0; mt < 4; mt++) {
                int m = wm + mt * 16 + g;
                af[mt][0] = As[m][ks * 8 + tig];
                af[mt][1] = As[m + 8][ks * 8 + tig];
                af[mt][2] = As[m][ks * 8 + tig + 4];
                af[mt][3] = As[m + 8][ks * 8 + tig + 4];
            }
#pragma unroll
            for (int nt = 0; nt < 4; nt++) {
                int n = wn + nt * 8 + g;
                bf[nt][0] = Bs[ks * 8 + tig][n];
                bf[nt][1] = Bs[ks * 8 + tig + 4][n];
            }
#pragma unroll
            for (int mt = 0; mt < 4; mt++)
#pragma unroll
                for (int nt = 0; nt < 4; nt++)
                    mma_tf32(acc[mt][nt], af[mt], bf[nt]);
        }
        __syncthreads();
        buf ^= 1;
    }

#pragma unroll
    for (int mt = 0; mt < 4; mt++) {
        int r0 = rowBase + wm + mt * 16 + g;
#pragma unroll
        for (int nt = 0; nt < 4; nt++) {
            int c = colBase + wn + nt * 8 + 2 * tig;
            float2 b2 = *(const float2*)(bias + c);
            float v00 = acc[mt][nt][0] + b2.x, v01 = acc[mt][nt][1] + b2.y;
            float v10 = acc[mt][nt][2] + b2.x, v11 = acc[mt][nt][3] + b2.y;
            float2 o0, o1;
            if (ROUND_OUT) {
                o0.x = __uint_as_float(f2tf(v00)); o0.y = __uint_as_float(f2tf(v01));
                o1.x = __uint_as_float(f2tf(v10)); o1.y = __uint_as_float(f2tf(v11));
            } else {
                o0.x = v00; o0.y = v01; o1.x = v10; o1.y = v11;
            }
            *(float2*)(C + (size_t)r0 * N + c)       = o0;
            *(float2*)(C + (size_t)(r0 + 8) * N + c) = o1;
        }
    }
}

// ---------------------------------------------------------------------------
// Causal flash attention, TF32 tensor cores, cp.async double-buffered K/V.
// Block: 64 queries (one (b,h)), 4 warps x 16 queries. Key tiles of 64.
// qkv holds tf32-rounded values. Output written tf32-rounded.
// Dyn smem: QP[64][68] | 2 x (Ks[64][68] + Vs[64][72]) = 89088 B.
// ---------------------------------------------------------------------------
#define QP_W    (64*68)
#define KS_W    (64*68)
#define VS_W    (64*72)
#define FSTAGE  (KS_W + VS_W)
#define FLASH_SMEM ((QP_W + 2*FSTAGE) * 4)

__global__ __launch_bounds__(128)
void flash_tf32(const float* __restrict__ qkv, float* __restrict__ out)
{
    extern __shared__ unsigned sm[];
    unsigned (*QP)[68] = (unsigned(*)[68])sm;

    const int b    = blockIdx.z;
    const int h    = blockIdx.y;
    const int qb   = gridDim.x - 1 - blockIdx.x;   // heavy blocks first
    const int tid  = threadIdx.x;
    const int lane = tid & 31;
    const int w    = tid >> 5;
    const int g    = lane >> 2;
    const int tig  = lane & 3;
    const int m0   = w * 16;

    const float SC = 0.125f * 1.44269504088896341f;  // scale * log2(e)

    auto loadKV = [&](int kb, int s) {
        unsigned* Ks = sm + QP_W + s * FSTAGE;
        unsigned* Vs = Ks + KS_W;
        const float* kp = qkv + (size_t)(b * TT + kb * 64) * C3 + CC + h * DH;
#pragma unroll
        for (int i = 0; i < 8; i++) {
            int idx = tid + i * 128;           // 0..1023
            int r = idx >> 4, c4 = idx & 15;
            const float* rp = kp + (size_t)r * C3 + c4 * 4;
            cp16(&Ks[r * 68 + c4 * 4], rp);
            cp16(&Vs[r * 72 + c4 * 4], rp + CC);
        }
    };

    // start K/V tile 0 immediately
    loadKV(0, 0);
    cp_commit();

    // ---- load Q tile (raw, pre-rounded) ----
    {
        const float* qp = qkv + (size_t)(b * TT + qb * 64) * C3 + h * DH;
#pragma unroll
        for (int i = 0; i < 8; i++) {
            int idx = tid + i * 128;
            int r = idx >> 4, c4 = idx & 15;
            *(float4*)&QP[r][c4 * 4] = *(const float4*)(qp + (size_t)r * C3 + c4 * 4);
        }
    }
    __syncthreads();

    // ---- persistent Q fragments ----
    unsigned qf[8][4];
#pragma unroll
    for (int kt = 0; kt < 8; kt++) {
        qf[kt][0] = QP[m0 + g][kt * 8 + tig];
        qf[kt][1] = QP[m0 + 8 + g][kt * 8 + tig];
        qf[kt][2] = QP[m0 + g][kt * 8 + tig + 4];
        qf[kt][3] = QP[m0 + 8 + g][kt * 8 + tig + 4];
    }

    float o[8][4];
#pragma unroll
    for (int nt = 0; nt < 8; nt++)
#pragma unroll
        for (int j = 0; j < 4; j++) o[nt][j] = 0.f;

    float mr0 = -1e30f, mr1 = -1e30f, l0 = 0.f, l1 = 0.f;
    const int qg0 = qb * 64 + m0 + g;
    const int qg1 = qg0 + 8;

    int buf = 0;
    for (int kb = 0; kb <= qb; kb++) {
        if (kb < qb) { loadKV(kb + 1, buf ^ 1); cp_commit(); cp_wait<1>(); }
        else         { cp_wait<0>(); }
        __syncthreads();   // K/V tile `buf` visible; qf extraction done (iter 0)

        unsigned (*Ks)[68] = (unsigned(*)[68])(sm + QP_W + buf * FSTAGE);
        unsigned (*Vs)[72] = (unsigned(*)[72])(sm + QP_W + buf * FSTAGE + KS_W);

        // ---- S = Q K^T (then scale) ----
        float s[8][4];
#pragma unroll
        for (int nt = 0; nt < 8; nt++) {
            s[nt][0] = s[nt][1] = s[nt][2] = s[nt][3] = 0.f;
#pragma unroll
            for (int kt = 0; kt < 8; kt++) {
                unsigned bb[2];
                bb[0] = Ks[nt * 8 + g][kt * 8 + tig];
                bb[1] = Ks[nt * 8 + g][kt * 8 + tig + 4];
                mma_tf32(s[nt], qf[kt], bb);
            }
            s[nt][0] *= SC; s[nt][1] *= SC; s[nt][2] *= SC; s[nt][3] *= SC;
        }

        // ---- causal mask (diagonal block only) ----
        if (kb == qb) {
#pragma unroll
            for (int nt = 0; nt < 8; nt++) {
                int kg = kb * 64 + nt * 8 + 2 * tig;
                if (kg > qg0)     s[nt][0] = -1e30f;
                if (kg + 1 > qg0) s[nt][1] = -1e30f;
                if (kg > qg1)     s[nt][2] = -1e30f;
                if (kg + 1 > qg1) s[nt][3] = -1e30f;
            }
        }

        // ---- online softmax (base-2) ----
        float vm0 = -1e30f, vm1 = -1e30f;
#pragma unroll
        for (int nt = 0; nt < 8; nt++) {
            vm0 = fmaxf(vm0, fmaxf(s[nt][0], s[nt][1]));
            vm1 = fmaxf(vm1, fmaxf(s[nt][2], s[nt][3]));
        }
        vm0 = fmaxf(vm0, __shfl_xor_sync(0xffffffffu, vm0, 1));
        vm0 = fmaxf(vm0, __shfl_xor_sync(0xffffffffu, vm0, 2));
        vm1 = fmaxf(vm1, __shfl_xor_sync(0xffffffffu, vm1, 1));
        vm1 = fmaxf(vm1, __shfl_xor_sync(0xffffffffu, vm1, 2));

        float mn0 = fmaxf(mr0, vm0), mn1 = fmaxf(mr1, vm1);
        float corr0 = ex2f(mr0 - mn0), corr1 = ex2f(mr1 - mn1);
        mr0 = mn0; mr1 = mn1;

        float sum0 = 0.f, sum1 = 0.f;
#pragma unroll
        for (int nt = 0; nt < 8; nt++) {
            s[nt][0] = ex2f(s[nt][0] - mn0);
            s[nt][1] = ex2f(s[nt][1] - mn0);
            s[nt][2] = ex2f(s[nt][2] - mn1);
            s[nt][3] = ex2f(s[nt][3] - mn1);
            sum0 += s[nt][0] + s[nt][1];
            sum1 += s[nt][2] + s[nt][3];
        }
        sum0 += __shfl_xor_sync(0xffffffffu, sum0, 1);
        sum0 += __shfl_xor_sync(0xffffffffu, sum0, 2);
        sum1 += __shfl_xor_sync(0xffffffffu, sum1, 1);
        sum1 += __shfl_xor_sync(0xffffffffu, sum1, 2);
        l0 = l0 * corr0 + sum0;
        l1 = l1 * corr1 + sum1;

#pragma unroll
        for (int nt = 0; nt < 8; nt++) {
            o[nt][0] *= corr0; o[nt][1] *= corr0;
            o[nt][2] *= corr1; o[nt][3] *= corr1;
        }

        // ---- stage P into QP (warp-local rows) ----
        __syncwarp();
#pragma unroll
        for (int nt = 0; nt < 8; nt++) {
            uint2 u0 = make_uint2(f2tf(s[nt][0]), f2tf(s[nt][1]));
            uint2 u1 = make_uint2(f2tf(s[nt][2]), f2tf(s[nt][3]));
            *(uint2*)&QP[m0 + g][nt * 8 + 2 * tig]     = u0;
            *(uint2*)&QP[m0 + 8 + g][nt * 8 + 2 * tig] = u1;
        }
        __syncwarp();

        // ---- O += P V ----
#pragma unroll
        for (int kt = 0; kt < 8; kt++) {
            unsigned pa[4];
            pa[0] = QP[m0 + g][kt * 8 + tig];
            pa[1] = QP[m0 + 8 + g][kt * 8 + tig];
            pa[2] = QP[m0 + g][kt * 8 + tig + 4];
            pa[3] = QP[m0 + 8 + g][kt * 8 + tig + 4];
#pragma unroll
            for (int nt = 0; nt < 8; nt++) {
                unsigned bb[2];
                bb[0] = Vs[kt * 8 + tig][nt * 8 + g];
                bb[1] = Vs[kt * 8 + tig + 4][nt * 8 + g];
                mma_tf32(o[nt], pa, bb);
            }
        }
        __syncthreads();   // all warps done with K/V `buf` before it is refilled
        buf ^= 1;
    }

    // ---- normalize and write out (tf32-rounded for the next GEMM) ----
    const float inv0 = 1.f / l0, inv1 = 1.f / l1;
    float* op0 = out + (size_t)(b * TT + qb * 64 + m0 + g) * CC + h * DH;
    float* op1 = op0 + (size_t)8 * CC;
#pragma unroll
    for (int nt = 0; nt < 8; nt++) {
        float2 r0, r1;
        r0.x = __uint_as_float(f2tf(o[nt][0] * inv0));
        r0.y = __uint_as_float(f2tf(o[nt][1] * inv0));
        r1.x = __uint_as_float(f2tf(o[nt][2] * inv1));
        r1.y = __uint_as_float(f2tf(o[nt][3] * inv1));
        *(float2*)(op0 + nt * 8 + 2 * tig) = r0;
        *(float2*)(op1 + nt * 8 + 2 * tig) = r1;
    }
}

// ---------------------------------------------------------------------------
// kernel_launch
// ---------------------------------------------------------------------------
extern "C" void kernel_launch(void* const* d_in, const int* in_sizes, int n_in,
                              void* d_out, int out_size)
{
    const float* x    = (const float*)d_in[0];
    // d_in[1] = mask (static causal; unused)
    const float* Wqkv = (const float*)d_in[2];
    const float* bqkv = (const float*)d_in[3];
    const float* Wout = (const float*)d_in[4];
    const float* bout = (const float*)d_in[5];
    float* out = (float*)d_out;

    float* qkv;   cudaGetSymbolAddress((void**)&qkv,   g_qkv);
    float* att;   cudaGetSymbolAddress((void**)&att,   g_att);
    float* xr;    cudaGetSymbolAddress((void**)&xr,    g_xr);
    float* wqkvr; cudaGetSymbolAddress((void**)&wqkvr, g_wqkvr);
    float* woutr; cudaGetSymbolAddress((void**)&woutr, g_woutr);

    static bool configured = false;
    if (!configured) {
        cudaFuncSetAttribute(gemm_tf32_ca<true>,
                             cudaFuncAttributeMaxDynamicSharedMemorySize, GEMM_SMEM);
        cudaFuncSetAttribute(gemm_tf32_ca<false>,
                             cudaFuncAttributeMaxDynamicSharedMemorySize, GEMM_SMEM);
        cudaFuncSetAttribute(flash_tf32,
                             cudaFuncAttributeMaxDynamicSharedMemorySize, FLASH_SMEM);
        configured = true;
    }

    // 0) round inputs to tf32 once
    round_tf32_kernel<<<(MM * CC / 4 + 255) / 256, 256>>>(x, xr, MM * CC / 4);
    round_tf32_kernel<<<(CC * C3 / 4 + 255) / 256, 256>>>(Wqkv, wqkvr, CC * C3 / 4);
    round_tf32_kernel<<<(CC * CC / 4 + 255) / 256, 256>>>(Wout, woutr, CC * CC / 4);

    // 1) QKV projection: [4096,768] @ [768,2304] + bias  (rounded output)
    {
        dim3 grid(C3 / 128, MM / 128);
        gemm_tf32_ca<true><<<grid, 256, GEMM_SMEM>>>(xr, wqkvr, bqkv, qkv, MM, C3, CC);
    }
    // 2) Causal multi-head attention (rounded output)
    {
        dim3 grid(TT / 64, NH, BB);
        flash_tf32<<<grid, 128, FLASH_SMEM>>>(qkv, att);
    }
    // 3) Output projection: [4096,768] @ [768,768] + bias (exact fp32 output)
    {
        dim3 grid(CC / 128, MM / 128);
        gemm_tf32_ca<false><<<grid, 256, GEMM_SMEM>>>(att, woutr, bout, out, MM, CC, CC);
    }
}